// round 13
// baseline (speedup 1.0000x reference)
#include <cuda_runtime.h>
#include <cuda_fp16.h>
#include <cstdint>

#define VOCABSZ 32000
#define EMBD    1024
#define HID     1024
#define G4      4096
#define NB      64
#define LSEQ    512
#define NCTA    128
#define NGRP    2          // batch groups
#define CPG     64         // CTAs per group
#define ROWS    32         // batch rows per group

// ---------------- device scratch (static; no cudaMalloc allowed) ----------------
__device__ __half g_Eb[(size_t)VOCABSZ * EMBD];          // E as fp16 (64 MB)
__device__ __half g_Bx[(size_t)G4 * 1024];               // W_x^T, [colp][k], gate-permuted (8 MB)
__device__ float  g_bias[G4];                            // permuted bias
__device__ float  g_Gx[(size_t)LSEQ * G4 * NB];          // x-gates, [t][c][n][loc64]
__device__ __half g_Hbuf[2][NB * HID];                   // H double buffer (fp16)
__device__ int    g_bar[NGRP * LSEQ];                    // per-group per-step counters

// gate-column permutation: colp = c*64 + loc ; gate = loc>>4, unit = c*16 + (loc&15)
__device__ __forceinline__ int perm_row(int colp) {
    int c = colp >> 6, loc = colp & 63;
    return ((loc >> 4) << 10) + c * 16 + (loc & 15);
}

// ---------------- mma / ldmatrix / cp.async helpers -----------------------------
__device__ __forceinline__ unsigned smem_u32(const void* p) {
    return (unsigned)__cvta_generic_to_shared(p);
}
__device__ __forceinline__ void ldmatrix_x4(unsigned* r, unsigned addr) {
    asm volatile("ldmatrix.sync.aligned.m8n8.x4.shared.b16 {%0,%1,%2,%3}, [%4];"
                 : "=r"(r[0]), "=r"(r[1]), "=r"(r[2]), "=r"(r[3]) : "r"(addr));
}
__device__ __forceinline__ void mma16816(float* d, const unsigned* a, unsigned b0, unsigned b1) {
    asm volatile("mma.sync.aligned.m16n8k16.row.col.f32.f16.f16.f32 "
                 "{%0,%1,%2,%3}, {%4,%5,%6,%7}, {%8,%9}, {%0,%1,%2,%3};"
                 : "+f"(d[0]), "+f"(d[1]), "+f"(d[2]), "+f"(d[3])
                 : "r"(a[0]), "r"(a[1]), "r"(a[2]), "r"(a[3]), "r"(b0), "r"(b1));
}
__device__ __forceinline__ void cp16(void* s, const void* g) {
    asm volatile("cp.async.cg.shared.global [%0], [%1], 16;"
                 :: "r"(smem_u32(s)), "l"(g) : "memory");
}
__device__ __forceinline__ void cp_commit() { asm volatile("cp.async.commit_group;" ::: "memory"); }
template <int N>
__device__ __forceinline__ void cp_wait() { asm volatile("cp.async.wait_group %0;" :: "n"(N) : "memory"); }

__device__ __forceinline__ void red_release(int* p, int v) {
    asm volatile("red.release.gpu.global.add.u32 [%0], %1;" :: "l"(p), "r"(v) : "memory");
}
__device__ __forceinline__ int ld_acquire(const int* p) {
    int v;
    asm volatile("ld.global.acquire.gpu.b32 %0, [%1];" : "=r"(v) : "l"(p) : "memory");
    return v;
}
__device__ __forceinline__ float sigf(float x) { return 1.0f / (1.0f + expf(-x)); }

// ---------------- prep: E -> fp16 ------------------------------------------------
__global__ __launch_bounds__(256) void k_cvt_e(const float* __restrict__ E) {
    size_t total8 = (size_t)VOCABSZ * EMBD / 8;
    size_t stride = (size_t)gridDim.x * blockDim.x;
    for (size_t i = (size_t)blockIdx.x * blockDim.x + threadIdx.x; i < total8; i += stride) {
        const float4* s = (const float4*)(E + i * 8);
        float4 v0 = s[0], v1 = s[1];
        __half2 h0 = __floats2half2_rn(v0.x, v0.y);
        __half2 h1 = __floats2half2_rn(v0.z, v0.w);
        __half2 h2 = __floats2half2_rn(v1.x, v1.y);
        __half2 h3 = __floats2half2_rn(v1.z, v1.w);
        uint4 o;
        o.x = *(unsigned*)&h0; o.y = *(unsigned*)&h1;
        o.z = *(unsigned*)&h2; o.w = *(unsigned*)&h3;
        ((uint4*)g_Eb)[i] = o;
    }
}

// ---------------- prep: pack Bx, bias, reset barriers & H0 -----------------------
__global__ __launch_bounds__(256) void k_pack(const float* __restrict__ W,
                                              const float* __restrict__ Wb) {
    int i0 = blockIdx.x * blockDim.x + threadIdx.x;
    int stride = gridDim.x * blockDim.x;
    for (int idx = i0; idx < G4 * 1024; idx += stride) {
        int colp = idx >> 10, k = idx & 1023;
        g_Bx[idx] = __float2half(W[(size_t)perm_row(colp) * 2048 + 1024 + k]);
    }
    for (int idx = i0; idx < G4; idx += stride) g_bias[idx] = Wb[perm_row(idx)];
    for (int idx = i0; idx < NGRP * LSEQ; idx += stride) g_bar[idx] = 0;
    for (int idx = i0; idx < NB * HID; idx += stride) g_Hbuf[0][idx] = __float2half(0.0f);
}

// ---------------- phase 1: Gx = embed(X) @ Wx^T + b -------------------------------
// CTA tile 256(m) x 256(n), K-chunk 32, 4-stage cp.async pipeline, 512 threads,
// 16 warps in a 4x4 grid (warp tile 64x64). Halves L2 traffic vs 128x128.
#define GX_STG  4
#define GX_STR  40
#define GX_TILE (256 * GX_STR)                   // halves per stage per matrix
#define GX_SMEM (GX_STG * 2 * GX_TILE * 2)       // 163840 B

__global__ __launch_bounds__(512, 1) void k_gx(const int* __restrict__ X) {
    extern __shared__ __align__(16) __half dsm[];
    __half* As = dsm;                            // [GX_STG][256][GX_STR]
    __half* Bs = dsm + GX_STG * GX_TILE;         // [GX_STG][256][GX_STR]
    __shared__ int   toks[256];
    __shared__ float bsm[256];

    int tid = threadIdx.x, lane = tid & 31, warp = tid >> 5;
    int wm = warp >> 2, wn = warp & 3;           // 4x4 warp grid
    int mblk = blockIdx.y * 256, nblk = blockIdx.x * 256;

    if (tid < 256) {
        int m = mblk + tid;                      // m = t*64 + n
        toks[tid] = X[(m & 63) * LSEQ + (m >> 6)];
        bsm[tid] = g_bias[nblk + tid];
    }
    __syncthreads();

    // stage loader: A,B each 256 rows x 32 halves; 2 cp16/thread per matrix
    auto issue = [&](int c) {
        __half* Ab = As + (c & (GX_STG - 1)) * GX_TILE;
        __half* Bb = Bs + (c & (GX_STG - 1)) * GX_TILE;
        int k0 = c * 32;
#pragma unroll
        for (int i = 0; i < 2; ++i) {
            int idx = tid + i * 512;             // 0..1023
            int row = idx >> 2, q = idx & 3;
            cp16(Ab + row * GX_STR + q * 8,
                 &g_Eb[(size_t)toks[row] * EMBD + k0 + q * 8]);
        }
#pragma unroll
        for (int i = 0; i < 2; ++i) {
            int idx = tid + i * 512;
            int row = idx >> 2, q = idx & 3;
            cp16(Bb + row * GX_STR + q * 8,
                 &g_Bx[(size_t)(nblk + row) * 1024 + k0 + q * 8]);
        }
        cp_commit();
    };

    float acc[4][8][4];
#pragma unroll
    for (int a = 0; a < 4; ++a)
#pragma unroll
        for (int b = 0; b < 8; ++b)
#pragma unroll
            for (int c = 0; c < 4; ++c) acc[a][b][c] = 0.0f;

    issue(0); issue(1); issue(2);

    for (int c = 0; c < 32; ++c) {
        if (c < 30)       cp_wait<2>();
        else if (c == 30) cp_wait<1>();
        else              cp_wait<0>();
        __syncthreads();

        if (c + 3 < 32) issue(c + 3);

        const __half* Ab = As + (c & (GX_STG - 1)) * GX_TILE;
        const __half* Bb = Bs + (c & (GX_STG - 1)) * GX_TILE;
#pragma unroll
        for (int ks = 0; ks < 2; ++ks) {
            unsigned a[4][4];
#pragma unroll
            for (int mt = 0; mt < 4; ++mt)
                ldmatrix_x4(a[mt], smem_u32(Ab + (wm * 64 + mt * 16 + (lane & 15)) * GX_STR
                                               + ks * 16 + (lane >> 4) * 8));
#pragma unroll
            for (int nt = 0; nt < 4; ++nt) {     // x4 B: 16 n-rows per ldsm
                unsigned b[4];
                ldmatrix_x4(b, smem_u32(Bb + (wn * 64 + nt * 16 + ((lane >> 4) << 3) + (lane & 7)) * GX_STR
                                           + ks * 16 + ((lane >> 3) & 1) * 8));
#pragma unroll
                for (int mt = 0; mt < 4; ++mt) {
                    mma16816(acc[mt][nt * 2],     a[mt], b[0], b[1]);
                    mma16816(acc[mt][nt * 2 + 1], a[mt], b[2], b[3]);
                }
            }
        }
    }

    // epilogue: add bias, store Gx[t][c][n][loc64]
#pragma unroll
    for (int mt = 0; mt < 4; ++mt) {
#pragma unroll
        for (int nt = 0; nt < 8; ++nt) {
            int mrow = mblk + wm * 64 + mt * 16 + (lane >> 2);
            int cloc = wn * 64 + nt * 8 + ((lane & 3) << 1);
            int colp = nblk + cloc;
            float b0 = bsm[cloc], b1 = bsm[cloc + 1];
            const float* c = acc[mt][nt];
#pragma unroll
            for (int rr = 0; rr < 2; ++rr) {
                int m = mrow + rr * 8;
                int t = m >> 6, n = m & 63;
                size_t off = (((size_t)t * CPG + (colp >> 6)) * NB + n) * 64 + (colp & 63);
                float2 v; v.x = c[rr * 2] + b0; v.y = c[rr * 2 + 1] + b1;
                *(float2*)&g_Gx[off] = v;
            }
        }
    }
}

// ---------------- phase 2: persistent recurrent kernel (R12 verbatim) -------------
#define HS_STRIDE 1032
#define SM_HS 0
#define SM_WS (ROWS * HS_STRIDE * 2)               // 66048
#define SMEM_REC (SM_WS + 64 * HS_STRIDE * 2)      // 198144

__global__ void __launch_bounds__(256, 1) k_rec(const float* __restrict__ W,
                                                float* __restrict__ out) {
    extern __shared__ __align__(16) char smem[];
    __half (*Hs)[HS_STRIDE] = (__half(*)[HS_STRIDE])(smem + SM_HS);   // [32][1032]
    __half (*Ws)[HS_STRIDE] = (__half(*)[HS_STRIDE])(smem + SM_WS);   // [64][1032]
    float* gsm = (float*)(smem + SM_HS);           // [4][32][65] floats, aliases Hs

    int g   = blockIdx.x >> 6;                     // group 0/1
    int c   = blockIdx.x & 63;                     // CTA index within group
    int tid = threadIdx.x, lane = tid & 31, warp = tid >> 5;
    int wk  = warp >> 1;                           // K-quarter 0..3
    int wn  = warp & 1;                            // n-half 0..1
    int cb  = wk * 256;

    // resident weight slice: Ws[loc][k] = W[(loc>>4)*1024 + c*16 + (loc&15)][k]
    for (int idx = tid; idx < 64 * 1024; idx += 256) {
        int loc = idx >> 10, k = idx & 1023;
        int wrow = ((loc >> 4) << 10) + c * 16 + (loc & 15);
        Ws[loc][k] = __float2half(W[(size_t)wrow * 2048 + k]);
    }
    __syncthreads();

    // elementwise ownership: em = batch row (0..31), units ej0, ej0+1 (of 16)
    int em = tid >> 3, ej0 = (tid & 7) * 2;
    float C0 = 0.0f, C1 = 0.0f;
    const float* gxbase = g_Gx + ((size_t)c * NB + g * ROWS + em) * 64 + ej0;

    // prologue: gx for t=0
    float2 gxr[4];
#pragma unroll
    for (int q = 0; q < 4; ++q) gxr[q] = *(const float2*)(gxbase + q * 16);

    for (int t = 0; t < LSEQ; ++t) {
        // stage own 128 H cols in 2 x 64-col groups (rows 0..31)
        const __half* Hg = g_Hbuf[t & 1] + (size_t)g * ROWS * 1024;
#pragma unroll
        for (int ch = 0; ch < 2; ++ch) {
            int colbase = cb + wn * 128 + ch * 64;
#pragma unroll
            for (int i = 0; i < 8; ++i) {
                int idx = i * 32 + lane;           // 0..255
                int row = idx >> 3;
                int col = colbase + (idx & 7) * 8;
                cp16(&Hs[row][col], Hg + row * 1024 + col);
            }
            cp_commit();
        }

        float acc[2][4][4];
#pragma unroll
        for (int a = 0; a < 2; ++a)
#pragma unroll
            for (int b = 0; b < 4; ++b)
#pragma unroll
                for (int cc = 0; cc < 4; ++cc) acc[a][b][cc] = 0.0f;

        // phase 0: own half, overlapped with the second refill group
#pragma unroll
        for (int sub = 0; sub < 2; ++sub) {
            if (sub == 0) cp_wait<1>(); else cp_wait<0>();
            __syncwarp();
            int k0b = cb + wn * 128 + sub * 64;
#pragma unroll
            for (int kt = 0; kt < 4; ++kt) {
                int k0 = k0b + kt * 16;
                unsigned a[2][4];
#pragma unroll
                for (int mt = 0; mt < 2; ++mt)
                    ldmatrix_x4(a[mt], smem_u32(&Hs[mt * 16 + (lane & 15)]
                                                  [k0 + (lane >> 4) * 8]));
#pragma unroll
                for (int bg = 0; bg < 2; ++bg) {
                    unsigned b[4];
                    ldmatrix_x4(b, smem_u32(&Ws[wn * 32 + bg * 16 + ((lane >> 4) << 3) + (lane & 7)]
                                              [k0 + ((lane >> 3) & 1) * 8]));
#pragma unroll
                    for (int mt = 0; mt < 2; ++mt) {
                        mma16816(acc[mt][bg * 2],     a[mt], b[0], b[1]);
                        mma16816(acc[mt][bg * 2 + 1], a[mt], b[2], b[3]);
                    }
                }
            }
        }

        // pair sync: partner's 128 cols staged & stable
        asm volatile("bar.sync %0, 64;" :: "r"(1 + wk) : "memory");

        // phase 1: partner half
        {
            int k0b = cb + (1 - wn) * 128;
#pragma unroll 4
            for (int kt = 0; kt < 8; ++kt) {
                int k0 = k0b + kt * 16;
                unsigned a[2][4];
#pragma unroll
                for (int mt = 0; mt < 2; ++mt)
                    ldmatrix_x4(a[mt], smem_u32(&Hs[mt * 16 + (lane & 15)]
                                                  [k0 + (lane >> 4) * 8]));
#pragma unroll
                for (int bg = 0; bg < 2; ++bg) {
                    unsigned b[4];
                    ldmatrix_x4(b, smem_u32(&Ws[wn * 32 + bg * 16 + ((lane >> 4) << 3) + (lane & 7)]
                                              [k0 + ((lane >> 3) & 1) * 8]));
#pragma unroll
                    for (int mt = 0; mt < 2; ++mt) {
                        mma16816(acc[mt][bg * 2],     a[mt], b[0], b[1]);
                        mma16816(acc[mt][bg * 2 + 1], a[mt], b[2], b[3]);
                    }
                }
            }
        }

        // all Hs reads done before gsm (alias) is written
        __syncthreads();
        {
            float* gp = gsm + wk * (32 * 65);
            int mrow = lane >> 2;
            int ncol = wn * 32 + ((lane & 3) << 1);
#pragma unroll
            for (int mt = 0; mt < 2; ++mt)
#pragma unroll
                for (int ng = 0; ng < 4; ++ng) {
                    const float* cc = acc[mt][ng];
                    int m = mrow + mt * 16, n = ncol + ng * 8;
                    gp[m * 65 + n]           = cc[0];
                    gp[m * 65 + n + 1]       = cc[1];
                    gp[(m + 8) * 65 + n]     = cc[2];
                    gp[(m + 8) * 65 + n + 1] = cc[3];
                }
        }
        __syncthreads();

        // elementwise: 4-way K-reduction + LSTM cell
        float s[4][2];
#pragma unroll
        for (int q = 0; q < 4; ++q) {
            float v0 = gxr[q].x, v1 = gxr[q].y;
            int base = em * 65 + q * 16 + ej0;
#pragma unroll
            for (int kq = 0; kq < 4; ++kq) {
                v0 += gsm[kq * (32 * 65) + base];
                v1 += gsm[kq * (32 * 65) + base + 1];
            }
            s[q][0] = v0; s[q][1] = v1;
        }
        float i0 = sigf(s[0][0]), f0 = sigf(s[1][0]), o0 = sigf(s[2][0]), gg0 = tanhf(s[3][0]);
        float i1 = sigf(s[0][1]), f1 = sigf(s[1][1]), o1 = sigf(s[2][1]), gg1 = tanhf(s[3][1]);
        C0 = f0 * C0 + i0 * gg0;
        C1 = f1 * C1 + i1 * gg1;
        float h0 = o0 * tanhf(C0), h1 = o1 * tanhf(C1);

        __half* Hn = g_Hbuf[(t & 1) ^ 1];
        int grow = g * ROWS + em;
        int hcol = c * 16 + ej0;
        *(__half2*)(Hn + grow * 1024 + hcol) = __floats2half2_rn(h0, h1);
        if (t == LSEQ - 1) {
            float2 ov; ov.x = h0; ov.y = h1;
            *(float2*)(out + grow * 1024 + hcol) = ov;
        }

        // prefetch next step's gx (hides LDG under barrier)
        int tn = (t + 1 < LSEQ) ? (t + 1) : t;
        const float* gxp = gxbase + (size_t)tn * CPG * NB * 64;
#pragma unroll
        for (int q = 0; q < 4; ++q) gxr[q] = *(const float2*)(gxp + q * 16);

        // grid barrier: release-RMW arrival (no membar), tid0 acquire-poll,
        // CTA-wide wake via syncthreads
        __syncthreads();
        if (tid == 0) {
            int* barp = &g_bar[g * LSEQ + t];
            red_release(barp, 1);
            while (ld_acquire(barp) < CPG) { }
        }
        __syncthreads();
    }
}

// ---------------- launch ----------------------------------------------------------
extern "C" void kernel_launch(void* const* d_in, const int* in_sizes, int n_in,
                              void* d_out, int out_size) {
    (void)in_sizes; (void)n_in; (void)out_size;
    const int*   X  = (const int*)d_in[0];
    const float* E  = (const float*)d_in[1];
    const float* W  = (const float*)d_in[2];
    const float* Wb = (const float*)d_in[3];
    float* out = (float*)d_out;

    cudaFuncSetAttribute(k_rec, cudaFuncAttributeMaxDynamicSharedMemorySize, SMEM_REC);
    cudaFuncSetAttribute(k_gx, cudaFuncAttributeMaxDynamicSharedMemorySize, GX_SMEM);

    k_cvt_e<<<2048, 256>>>(E);
    k_pack<<<1024, 256>>>(W, Wb);
    k_gx<<<dim3(16, 128), 512, GX_SMEM>>>(X);
    k_rec<<<NCTA, 256, SMEM_REC>>>(W, out);
}

// round 14
// speedup vs baseline: 1.2505x; 1.2505x over previous
#include <cuda_runtime.h>
#include <cuda_fp16.h>
#include <cstdint>

#define VOCABSZ 32000
#define EMBD    1024
#define HID     1024
#define G4      4096
#define NB      64
#define LSEQ    512
#define NCTA    128
#define NGRP    2          // batch groups
#define CPG     64         // CTAs per group
#define ROWS    32         // batch rows per group

// ---------------- device scratch (static; no cudaMalloc allowed) ----------------
__device__ __half g_Eb[(size_t)VOCABSZ * EMBD];          // E as fp16 (64 MB)
__device__ __half g_Bx[(size_t)G4 * 1024];               // W_x^T, [colp][k], gate-permuted (8 MB)
__device__ float  g_bias[G4];                            // permuted bias
__device__ float  g_Gx[(size_t)LSEQ * G4 * NB];          // x-gates, [t][c][n][loc64]
__device__ __half g_Hbuf[2][NB * HID];                   // H double buffer (fp16)
__device__ int    g_bar[NGRP * LSEQ];                    // per-group per-step counters

// gate-column permutation: colp = c*64 + loc ; gate = loc>>4, unit = c*16 + (loc&15)
__device__ __forceinline__ int perm_row(int colp) {
    int c = colp >> 6, loc = colp & 63;
    return ((loc >> 4) << 10) + c * 16 + (loc & 15);
}

// ---------------- mma / ldmatrix / cp.async helpers -----------------------------
__device__ __forceinline__ unsigned smem_u32(const void* p) {
    return (unsigned)__cvta_generic_to_shared(p);
}
__device__ __forceinline__ void ldmatrix_x4(unsigned* r, unsigned addr) {
    asm volatile("ldmatrix.sync.aligned.m8n8.x4.shared.b16 {%0,%1,%2,%3}, [%4];"
                 : "=r"(r[0]), "=r"(r[1]), "=r"(r[2]), "=r"(r[3]) : "r"(addr));
}
__device__ __forceinline__ void mma16816(float* d, const unsigned* a, unsigned b0, unsigned b1) {
    asm volatile("mma.sync.aligned.m16n8k16.row.col.f32.f16.f16.f32 "
                 "{%0,%1,%2,%3}, {%4,%5,%6,%7}, {%8,%9}, {%0,%1,%2,%3};"
                 : "+f"(d[0]), "+f"(d[1]), "+f"(d[2]), "+f"(d[3])
                 : "r"(a[0]), "r"(a[1]), "r"(a[2]), "r"(a[3]), "r"(b0), "r"(b1));
}
__device__ __forceinline__ void cp16(void* s, const void* g) {
    asm volatile("cp.async.cg.shared.global [%0], [%1], 16;"
                 :: "r"(smem_u32(s)), "l"(g) : "memory");
}
__device__ __forceinline__ void cp_commit() { asm volatile("cp.async.commit_group;" ::: "memory"); }
template <int N>
__device__ __forceinline__ void cp_wait() { asm volatile("cp.async.wait_group %0;" :: "n"(N) : "memory"); }

__device__ __forceinline__ void red_release(int* p, int v) {
    asm volatile("red.release.gpu.global.add.u32 [%0], %1;" :: "l"(p), "r"(v) : "memory");
}
__device__ __forceinline__ int ld_acquire(const int* p) {
    int v;
    asm volatile("ld.global.acquire.gpu.b32 %0, [%1];" : "=r"(v) : "l"(p) : "memory");
    return v;
}
__device__ __forceinline__ float sigf(float x) { return 1.0f / (1.0f + expf(-x)); }

// ---------------- prep: E -> fp16 ------------------------------------------------
__global__ __launch_bounds__(256) void k_cvt_e(const float* __restrict__ E) {
    size_t total8 = (size_t)VOCABSZ * EMBD / 8;
    size_t stride = (size_t)gridDim.x * blockDim.x;
    for (size_t i = (size_t)blockIdx.x * blockDim.x + threadIdx.x; i < total8; i += stride) {
        const float4* s = (const float4*)(E + i * 8);
        float4 v0 = s[0], v1 = s[1];
        __half2 h0 = __floats2half2_rn(v0.x, v0.y);
        __half2 h1 = __floats2half2_rn(v0.z, v0.w);
        __half2 h2 = __floats2half2_rn(v1.x, v1.y);
        __half2 h3 = __floats2half2_rn(v1.z, v1.w);
        uint4 o;
        o.x = *(unsigned*)&h0; o.y = *(unsigned*)&h1;
        o.z = *(unsigned*)&h2; o.w = *(unsigned*)&h3;
        ((uint4*)g_Eb)[i] = o;
    }
}

// ---------------- prep: pack Bx, bias, reset barriers & H0 -----------------------
__global__ __launch_bounds__(256) void k_pack(const float* __restrict__ W,
                                              const float* __restrict__ Wb) {
    int i0 = blockIdx.x * blockDim.x + threadIdx.x;
    int stride = gridDim.x * blockDim.x;
    for (int idx = i0; idx < G4 * 1024; idx += stride) {
        int colp = idx >> 10, k = idx & 1023;
        g_Bx[idx] = __float2half(W[(size_t)perm_row(colp) * 2048 + 1024 + k]);
    }
    for (int idx = i0; idx < G4; idx += stride) g_bias[idx] = Wb[perm_row(idx)];
    for (int idx = i0; idx < NGRP * LSEQ; idx += stride) g_bar[idx] = 0;
    for (int idx = i0; idx < NB * HID; idx += stride) g_Hbuf[0][idx] = __float2half(0.0f);
}

// ---------------- phase 1: Gx = embed(X) @ Wx^T + b -------------------------------
// CTA tile 128(m) x 256(n), K-chunk 32, 3-stage cp.async, 512 threads, 16 warps
// (2x8 grid, warp tile 64x32 -> acc 64 regs, fits 128-reg cap, NO SPILL).
// L2 traffic 3 GB vs 4 GB for 128x128 tiles.
#define GX_STG   3
#define GX_STR   40
#define GX_ATILE (128 * GX_STR)                  // halves per A stage
#define GX_BTILE (256 * GX_STR)                  // halves per B stage
#define GX_SMEM  (GX_STG * (GX_ATILE + GX_BTILE) * 2)   // 92160 B

__global__ __launch_bounds__(512, 1) void k_gx(const int* __restrict__ X) {
    extern __shared__ __align__(16) __half dsm[];
    __half* As = dsm;                            // [GX_STG][128][GX_STR]
    __half* Bs = dsm + GX_STG * GX_ATILE;        // [GX_STG][256][GX_STR]
    __shared__ int   toks[128];
    __shared__ float bsm[256];

    int tid = threadIdx.x, lane = tid & 31, warp = tid >> 5;
    int wm = warp >> 3, wn = warp & 7;           // 2x8 warp grid, warp tile 64x32
    int mblk = blockIdx.y * 128, nblk = blockIdx.x * 256;

    if (tid < 128) {
        int m = mblk + tid;                      // m = t*64 + n
        toks[tid] = X[(m & 63) * LSEQ + (m >> 6)];
    }
    if (tid < 256) bsm[tid] = g_bias[nblk + tid];
    __syncthreads();

    // stage loader: A 128x32 (1 cp16/thread), B 256x32 (2 cp16/thread)
    auto issue = [&](int c) {
        int buf = c % GX_STG;
        __half* Ab = As + buf * GX_ATILE;
        __half* Bb = Bs + buf * GX_BTILE;
        int k0 = c * 32;
        {
            int row = tid >> 2, q = tid & 3;     // 0..511 -> 128 rows x 4
            cp16(Ab + row * GX_STR + q * 8,
                 &g_Eb[(size_t)toks[row] * EMBD + k0 + q * 8]);
        }
#pragma unroll
        for (int i = 0; i < 2; ++i) {
            int idx = tid + i * 512;             // 0..1023 -> 256 rows x 4
            int row = idx >> 2, q = idx & 3;
            cp16(Bb + row * GX_STR + q * 8,
                 &g_Bx[(size_t)(nblk + row) * 1024 + k0 + q * 8]);
        }
        cp_commit();
    };

    float acc[4][4][4];
#pragma unroll
    for (int a = 0; a < 4; ++a)
#pragma unroll
        for (int b = 0; b < 4; ++b)
#pragma unroll
            for (int c = 0; c < 4; ++c) acc[a][b][c] = 0.0f;

    issue(0); issue(1);

    for (int c = 0; c < 32; ++c) {
        if (c < 31) cp_wait<1>(); else cp_wait<0>();
        __syncthreads();                         // all warps done with buf (c-1)%3

        if (c + 2 < 32) issue(c + 2);

        const __half* Ab = As + (c % GX_STG) * GX_ATILE;
        const __half* Bb = Bs + (c % GX_STG) * GX_BTILE;
#pragma unroll
        for (int ks = 0; ks < 2; ++ks) {
            unsigned a[4][4];
#pragma unroll
            for (int mt = 0; mt < 4; ++mt)
                ldmatrix_x4(a[mt], smem_u32(Ab + (wm * 64 + mt * 16 + (lane & 15)) * GX_STR
                                               + ks * 16 + (lane >> 4) * 8));
#pragma unroll
            for (int nt = 0; nt < 2; ++nt) {     // x4 B: 16 n-rows per ldsm
                unsigned b[4];
                ldmatrix_x4(b, smem_u32(Bb + (wn * 32 + nt * 16 + ((lane >> 4) << 3) + (lane & 7)) * GX_STR
                                           + ks * 16 + ((lane >> 3) & 1) * 8));
#pragma unroll
                for (int mt = 0; mt < 4; ++mt) {
                    mma16816(acc[mt][nt * 2],     a[mt], b[0], b[1]);
                    mma16816(acc[mt][nt * 2 + 1], a[mt], b[2], b[3]);
                }
            }
        }
    }

    // epilogue: add bias, store Gx[t][c][n][loc64]
#pragma unroll
    for (int mt = 0; mt < 4; ++mt) {
#pragma unroll
        for (int nt = 0; nt < 4; ++nt) {
            int mrow = mblk + wm * 64 + mt * 16 + (lane >> 2);
            int cloc = wn * 32 + nt * 8 + ((lane & 3) << 1);
            int colp = nblk + cloc;
            float b0 = bsm[cloc], b1 = bsm[cloc + 1];
            const float* c = acc[mt][nt];
#pragma unroll
            for (int rr = 0; rr < 2; ++rr) {
                int m = mrow + rr * 8;
                int t = m >> 6, n = m & 63;
                size_t off = (((size_t)t * CPG + (colp >> 6)) * NB + n) * 64 + (colp & 63);
                float2 v; v.x = c[rr * 2] + b0; v.y = c[rr * 2 + 1] + b1;
                *(float2*)&g_Gx[off] = v;
            }
        }
    }
}

// ---------------- phase 2: persistent recurrent kernel (R12 verbatim) -------------
#define HS_STRIDE 1032
#define SM_HS 0
#define SM_WS (ROWS * HS_STRIDE * 2)               // 66048
#define SMEM_REC (SM_WS + 64 * HS_STRIDE * 2)      // 198144

__global__ void __launch_bounds__(256, 1) k_rec(const float* __restrict__ W,
                                                float* __restrict__ out) {
    extern __shared__ __align__(16) char smem[];
    __half (*Hs)[HS_STRIDE] = (__half(*)[HS_STRIDE])(smem + SM_HS);   // [32][1032]
    __half (*Ws)[HS_STRIDE] = (__half(*)[HS_STRIDE])(smem + SM_WS);   // [64][1032]
    float* gsm = (float*)(smem + SM_HS);           // [4][32][65] floats, aliases Hs

    int g   = blockIdx.x >> 6;                     // group 0/1
    int c   = blockIdx.x & 63;                     // CTA index within group
    int tid = threadIdx.x, lane = tid & 31, warp = tid >> 5;
    int wk  = warp >> 1;                           // K-quarter 0..3
    int wn  = warp & 1;                            // n-half 0..1
    int cb  = wk * 256;

    // resident weight slice: Ws[loc][k] = W[(loc>>4)*1024 + c*16 + (loc&15)][k]
    for (int idx = tid; idx < 64 * 1024; idx += 256) {
        int loc = idx >> 10, k = idx & 1023;
        int wrow = ((loc >> 4) << 10) + c * 16 + (loc & 15);
        Ws[loc][k] = __float2half(W[(size_t)wrow * 2048 + k]);
    }
    __syncthreads();

    // elementwise ownership: em = batch row (0..31), units ej0, ej0+1 (of 16)
    int em = tid >> 3, ej0 = (tid & 7) * 2;
    float C0 = 0.0f, C1 = 0.0f;
    const float* gxbase = g_Gx + ((size_t)c * NB + g * ROWS + em) * 64 + ej0;

    // prologue: gx for t=0
    float2 gxr[4];
#pragma unroll
    for (int q = 0; q < 4; ++q) gxr[q] = *(const float2*)(gxbase + q * 16);

    for (int t = 0; t < LSEQ; ++t) {
        // stage own 128 H cols in 2 x 64-col groups (rows 0..31)
        const __half* Hg = g_Hbuf[t & 1] + (size_t)g * ROWS * 1024;
#pragma unroll
        for (int ch = 0; ch < 2; ++ch) {
            int colbase = cb + wn * 128 + ch * 64;
#pragma unroll
            for (int i = 0; i < 8; ++i) {
                int idx = i * 32 + lane;           // 0..255
                int row = idx >> 3;
                int col = colbase + (idx & 7) * 8;
                cp16(&Hs[row][col], Hg + row * 1024 + col);
            }
            cp_commit();
        }

        float acc[2][4][4];
#pragma unroll
        for (int a = 0; a < 2; ++a)
#pragma unroll
            for (int b = 0; b < 4; ++b)
#pragma unroll
                for (int cc = 0; cc < 4; ++cc) acc[a][b][cc] = 0.0f;

        // phase 0: own half, overlapped with the second refill group
#pragma unroll
        for (int sub = 0; sub < 2; ++sub) {
            if (sub == 0) cp_wait<1>(); else cp_wait<0>();
            __syncwarp();
            int k0b = cb + wn * 128 + sub * 64;
#pragma unroll
            for (int kt = 0; kt < 4; ++kt) {
                int k0 = k0b + kt * 16;
                unsigned a[2][4];
#pragma unroll
                for (int mt = 0; mt < 2; ++mt)
                    ldmatrix_x4(a[mt], smem_u32(&Hs[mt * 16 + (lane & 15)]
                                                  [k0 + (lane >> 4) * 8]));
#pragma unroll
                for (int bg = 0; bg < 2; ++bg) {
                    unsigned b[4];
                    ldmatrix_x4(b, smem_u32(&Ws[wn * 32 + bg * 16 + ((lane >> 4) << 3) + (lane & 7)]
                                              [k0 + ((lane >> 3) & 1) * 8]));
#pragma unroll
                    for (int mt = 0; mt < 2; ++mt) {
                        mma16816(acc[mt][bg * 2],     a[mt], b[0], b[1]);
                        mma16816(acc[mt][bg * 2 + 1], a[mt], b[2], b[3]);
                    }
                }
            }
        }

        // pair sync: partner's 128 cols staged & stable
        asm volatile("bar.sync %0, 64;" :: "r"(1 + wk) : "memory");

        // phase 1: partner half
        {
            int k0b = cb + (1 - wn) * 128;
#pragma unroll 4
            for (int kt = 0; kt < 8; ++kt) {
                int k0 = k0b + kt * 16;
                unsigned a[2][4];
#pragma unroll
                for (int mt = 0; mt < 2; ++mt)
                    ldmatrix_x4(a[mt], smem_u32(&Hs[mt * 16 + (lane & 15)]
                                                  [k0 + (lane >> 4) * 8]));
#pragma unroll
                for (int bg = 0; bg < 2; ++bg) {
                    unsigned b[4];
                    ldmatrix_x4(b, smem_u32(&Ws[wn * 32 + bg * 16 + ((lane >> 4) << 3) + (lane & 7)]
                                              [k0 + ((lane >> 3) & 1) * 8]));
#pragma unroll
                    for (int mt = 0; mt < 2; ++mt) {
                        mma16816(acc[mt][bg * 2],     a[mt], b[0], b[1]);
                        mma16816(acc[mt][bg * 2 + 1], a[mt], b[2], b[3]);
                    }
                }
            }
        }

        // all Hs reads done before gsm (alias) is written
        __syncthreads();
        {
            float* gp = gsm + wk * (32 * 65);
            int mrow = lane >> 2;
            int ncol = wn * 32 + ((lane & 3) << 1);
#pragma unroll
            for (int mt = 0; mt < 2; ++mt)
#pragma unroll
                for (int ng = 0; ng < 4; ++ng) {
                    const float* cc = acc[mt][ng];
                    int m = mrow + mt * 16, n = ncol + ng * 8;
                    gp[m * 65 + n]           = cc[0];
                    gp[m * 65 + n + 1]       = cc[1];
                    gp[(m + 8) * 65 + n]     = cc[2];
                    gp[(m + 8) * 65 + n + 1] = cc[3];
                }
        }
        __syncthreads();

        // elementwise: 4-way K-reduction + LSTM cell
        float s[4][2];
#pragma unroll
        for (int q = 0; q < 4; ++q) {
            float v0 = gxr[q].x, v1 = gxr[q].y;
            int base = em * 65 + q * 16 + ej0;
#pragma unroll
            for (int kq = 0; kq < 4; ++kq) {
                v0 += gsm[kq * (32 * 65) + base];
                v1 += gsm[kq * (32 * 65) + base + 1];
            }
            s[q][0] = v0; s[q][1] = v1;
        }
        float i0 = sigf(s[0][0]), f0 = sigf(s[1][0]), o0 = sigf(s[2][0]), gg0 = tanhf(s[3][0]);
        float i1 = sigf(s[0][1]), f1 = sigf(s[1][1]), o1 = sigf(s[2][1]), gg1 = tanhf(s[3][1]);
        C0 = f0 * C0 + i0 * gg0;
        C1 = f1 * C1 + i1 * gg1;
        float h0 = o0 * tanhf(C0), h1 = o1 * tanhf(C1);

        __half* Hn = g_Hbuf[(t & 1) ^ 1];
        int grow = g * ROWS + em;
        int hcol = c * 16 + ej0;
        *(__half2*)(Hn + grow * 1024 + hcol) = __floats2half2_rn(h0, h1);
        if (t == LSEQ - 1) {
            float2 ov; ov.x = h0; ov.y = h1;
            *(float2*)(out + grow * 1024 + hcol) = ov;
        }

        // prefetch next step's gx (hides LDG under barrier)
        int tn = (t + 1 < LSEQ) ? (t + 1) : t;
        const float* gxp = gxbase + (size_t)tn * CPG * NB * 64;
#pragma unroll
        for (int q = 0; q < 4; ++q) gxr[q] = *(const float2*)(gxp + q * 16);

        // grid barrier: release-RMW arrival (no membar), tid0 acquire-poll,
        // CTA-wide wake via syncthreads
        __syncthreads();
        if (tid == 0) {
            int* barp = &g_bar[g * LSEQ + t];
            red_release(barp, 1);
            while (ld_acquire(barp) < CPG) { }
        }
        __syncthreads();
    }
}

// ---------------- launch ----------------------------------------------------------
extern "C" void kernel_launch(void* const* d_in, const int* in_sizes, int n_in,
                              void* d_out, int out_size) {
    (void)in_sizes; (void)n_in; (void)out_size;
    const int*   X  = (const int*)d_in[0];
    const float* E  = (const float*)d_in[1];
    const float* W  = (const float*)d_in[2];
    const float* Wb = (const float*)d_in[3];
    float* out = (float*)d_out;

    cudaFuncSetAttribute(k_rec, cudaFuncAttributeMaxDynamicSharedMemorySize, SMEM_REC);
    cudaFuncSetAttribute(k_gx, cudaFuncAttributeMaxDynamicSharedMemorySize, GX_SMEM);

    k_cvt_e<<<2048, 256>>>(E);
    k_pack<<<1024, 256>>>(W, Wb);
    k_gx<<<dim3(16, 256), 512, GX_SMEM>>>(X);
    k_rec<<<NCTA, 256, SMEM_REC>>>(W, out);
}

// round 15
// speedup vs baseline: 1.3801x; 1.1037x over previous
#include <cuda_runtime.h>
#include <cuda_fp16.h>
#include <cstdint>

#define VOCABSZ 32000
#define EMBD    1024
#define HID     1024
#define G4      4096
#define NB      64
#define LSEQ    512
#define NCTA    128
#define NGRP    2          // batch groups
#define CPG     64         // CTAs per group
#define ROWS    32         // batch rows per group

// ---------------- device scratch (static; no cudaMalloc allowed) ----------------
__device__ __half g_Eb[(size_t)VOCABSZ * EMBD];          // E as fp16 (64 MB)
__device__ __half g_Bx[(size_t)G4 * 1024];               // W_x^T, [colp][k], gate-permuted (8 MB)
__device__ float  g_bias[G4];                            // permuted bias
__device__ float  g_Gx[(size_t)LSEQ * G4 * NB];          // x-gates, [t][c][n][loc64]
__device__ __half g_Hbuf[2][NB * HID];                   // H double buffer (fp16)
__device__ int    g_bar[NGRP * LSEQ];                    // per-group per-step counters

// gate-column permutation: colp = c*64 + loc ; gate = loc>>4, unit = c*16 + (loc&15)
__device__ __forceinline__ int perm_row(int colp) {
    int c = colp >> 6, loc = colp & 63;
    return ((loc >> 4) << 10) + c * 16 + (loc & 15);
}

// ---------------- mma / ldmatrix / cp.async helpers -----------------------------
__device__ __forceinline__ unsigned smem_u32(const void* p) {
    return (unsigned)__cvta_generic_to_shared(p);
}
__device__ __forceinline__ void ldmatrix_x4(unsigned* r, unsigned addr) {
    asm volatile("ldmatrix.sync.aligned.m8n8.x4.shared.b16 {%0,%1,%2,%3}, [%4];"
                 : "=r"(r[0]), "=r"(r[1]), "=r"(r[2]), "=r"(r[3]) : "r"(addr));
}
__device__ __forceinline__ void ldmatrix_x2(unsigned* r, unsigned addr) {
    asm volatile("ldmatrix.sync.aligned.m8n8.x2.shared.b16 {%0,%1}, [%2];"
                 : "=r"(r[0]), "=r"(r[1]) : "r"(addr));
}
__device__ __forceinline__ void mma16816(float* d, const unsigned* a, unsigned b0, unsigned b1) {
    asm volatile("mma.sync.aligned.m16n8k16.row.col.f32.f16.f16.f32 "
                 "{%0,%1,%2,%3}, {%4,%5,%6,%7}, {%8,%9}, {%0,%1,%2,%3};"
                 : "+f"(d[0]), "+f"(d[1]), "+f"(d[2]), "+f"(d[3])
                 : "r"(a[0]), "r"(a[1]), "r"(a[2]), "r"(a[3]), "r"(b0), "r"(b1));
}
__device__ __forceinline__ void cp16(void* s, const void* g) {
    asm volatile("cp.async.cg.shared.global [%0], [%1], 16;"
                 :: "r"(smem_u32(s)), "l"(g) : "memory");
}
__device__ __forceinline__ void cp_commit() { asm volatile("cp.async.commit_group;" ::: "memory"); }
template <int N>
__device__ __forceinline__ void cp_wait() { asm volatile("cp.async.wait_group %0;" :: "n"(N) : "memory"); }

__device__ __forceinline__ void red_release(int* p, int v) {
    asm volatile("red.release.gpu.global.add.u32 [%0], %1;" :: "l"(p), "r"(v) : "memory");
}
__device__ __forceinline__ int ld_acquire(const int* p) {
    int v;
    asm volatile("ld.global.acquire.gpu.b32 %0, [%1];" : "=r"(v) : "l"(p) : "memory");
    return v;
}
// fast transcendentals (MUFU-based): ~2 ulp, far below the fp16 noise floor
__device__ __forceinline__ float sigf(float x) {
    return __fdividef(1.0f, 1.0f + __expf(-x));
}
__device__ __forceinline__ float tanhfast(float x) {
    float e = __expf(2.0f * x);
    return 1.0f - __fdividef(2.0f, e + 1.0f);
}

// ---------------- prep: E -> fp16 ------------------------------------------------
__global__ __launch_bounds__(256) void k_cvt_e(const float* __restrict__ E) {
    size_t total8 = (size_t)VOCABSZ * EMBD / 8;
    size_t stride = (size_t)gridDim.x * blockDim.x;
    for (size_t i = (size_t)blockIdx.x * blockDim.x + threadIdx.x; i < total8; i += stride) {
        const float4* s = (const float4*)(E + i * 8);
        float4 v0 = s[0], v1 = s[1];
        __half2 h0 = __floats2half2_rn(v0.x, v0.y);
        __half2 h1 = __floats2half2_rn(v0.z, v0.w);
        __half2 h2 = __floats2half2_rn(v1.x, v1.y);
        __half2 h3 = __floats2half2_rn(v1.z, v1.w);
        uint4 o;
        o.x = *(unsigned*)&h0; o.y = *(unsigned*)&h1;
        o.z = *(unsigned*)&h2; o.w = *(unsigned*)&h3;
        ((uint4*)g_Eb)[i] = o;
    }
}

// ---------------- prep: pack Bx, bias, reset barriers & H0 -----------------------
__global__ __launch_bounds__(256) void k_pack(const float* __restrict__ W,
                                              const float* __restrict__ Wb) {
    int i0 = blockIdx.x * blockDim.x + threadIdx.x;
    int stride = gridDim.x * blockDim.x;
    for (int idx = i0; idx < G4 * 1024; idx += stride) {
        int colp = idx >> 10, k = idx & 1023;
        g_Bx[idx] = __float2half(W[(size_t)perm_row(colp) * 2048 + 1024 + k]);
    }
    for (int idx = i0; idx < G4; idx += stride) g_bias[idx] = Wb[perm_row(idx)];
    for (int idx = i0; idx < NGRP * LSEQ; idx += stride) g_bar[idx] = 0;
    for (int idx = i0; idx < NB * HID; idx += stride) g_Hbuf[0][idx] = __float2half(0.0f);
}

// ---------------- phase 1: Gx = embed(X) @ Wx^T + b (R12-proven, at HMMA ceiling) -
#define GX_STG  4
#define GX_STR  40
#define GX_TILE (128 * GX_STR)
#define GX_SMEM (GX_STG * 2 * GX_TILE * 2)       // 81920 B

__global__ __launch_bounds__(256, 2) void k_gx(const int* __restrict__ X) {
    extern __shared__ __align__(16) __half dsm[];
    __half* As = dsm;
    __half* Bs = dsm + GX_STG * GX_TILE;
    __shared__ int   toks[128];
    __shared__ float bsm[128];

    int tid = threadIdx.x, lane = tid & 31, warp = tid >> 5;
    int wm = warp >> 1, wn = warp & 1;
    int mblk = blockIdx.y * 128, nblk = blockIdx.x * 128;

    if (tid < 128) {
        int m = mblk + tid;                      // m = t*64 + n
        toks[tid] = X[(m & 63) * LSEQ + (m >> 6)];
        bsm[tid] = g_bias[nblk + tid];
    }
    __syncthreads();

    auto issue = [&](int c) {
        __half* Ab = As + (c & (GX_STG - 1)) * GX_TILE;
        __half* Bb = Bs + (c & (GX_STG - 1)) * GX_TILE;
        int k0 = c * 32;
#pragma unroll
        for (int i = 0; i < 2; ++i) {
            int idx = tid + i * 256;
            int row = idx >> 2, q = idx & 3;
            cp16(Ab + row * GX_STR + q * 8,
                 &g_Eb[(size_t)toks[row] * EMBD + k0 + q * 8]);
        }
#pragma unroll
        for (int i = 0; i < 2; ++i) {
            int idx = tid + i * 256;
            int row = idx >> 2, q = idx & 3;
            cp16(Bb + row * GX_STR + q * 8,
                 &g_Bx[(size_t)(nblk + row) * 1024 + k0 + q * 8]);
        }
        cp_commit();
    };

    float acc[2][8][4];
#pragma unroll
    for (int a = 0; a < 2; ++a)
#pragma unroll
        for (int b = 0; b < 8; ++b)
#pragma unroll
            for (int c = 0; c < 4; ++c) acc[a][b][c] = 0.0f;

    issue(0); issue(1); issue(2);

    for (int c = 0; c < 32; ++c) {
        if (c < 30)       cp_wait<2>();
        else if (c == 30) cp_wait<1>();
        else              cp_wait<0>();
        __syncthreads();

        if (c + 3 < 32) issue(c + 3);

        const __half* Ab = As + (c & (GX_STG - 1)) * GX_TILE;
        const __half* Bb = Bs + (c & (GX_STG - 1)) * GX_TILE;
#pragma unroll
        for (int ks = 0; ks < 2; ++ks) {
            unsigned a[2][4];
#pragma unroll
            for (int mt = 0; mt < 2; ++mt)
                ldmatrix_x4(a[mt], smem_u32(Ab + (wm * 32 + mt * 16 + (lane & 15)) * GX_STR
                                               + ks * 16 + (lane >> 4) * 8));
#pragma unroll
            for (int nt = 0; nt < 4; ++nt) {     // x4 B: 16 n-rows per ldsm
                unsigned b[4];
                ldmatrix_x4(b, smem_u32(Bb + (wn * 64 + nt * 16 + ((lane >> 4) << 3) + (lane & 7)) * GX_STR
                                           + ks * 16 + ((lane >> 3) & 1) * 8));
                mma16816(acc[0][nt * 2],     a[0], b[0], b[1]);
                mma16816(acc[1][nt * 2],     a[1], b[0], b[1]);
                mma16816(acc[0][nt * 2 + 1], a[0], b[2], b[3]);
                mma16816(acc[1][nt * 2 + 1], a[1], b[2], b[3]);
            }
        }
    }

    // epilogue: add bias, store Gx[t][c][n][loc64]
#pragma unroll
    for (int mt = 0; mt < 2; ++mt) {
#pragma unroll
        for (int nt = 0; nt < 8; ++nt) {
            int mrow = mblk + wm * 32 + mt * 16 + (lane >> 2);
            int cloc = wn * 64 + nt * 8 + ((lane & 3) << 1);
            int colp = nblk + cloc;
            float b0 = bsm[cloc], b1 = bsm[cloc + 1];
            const float* c = acc[mt][nt];
#pragma unroll
            for (int rr = 0; rr < 2; ++rr) {
                int m = mrow + rr * 8;
                int t = m >> 6, n = m & 63;
                size_t off = (((size_t)t * CPG + (colp >> 6)) * NB + n) * 64 + (colp & 63);
                float2 v; v.x = c[rr * 2] + b0; v.y = c[rr * 2 + 1] + b1;
                *(float2*)&g_Gx[off] = v;
            }
        }
    }
}

// ---------------- phase 2: persistent recurrent kernel (R12 + fast cell) ---------
#define HS_STRIDE 1032
#define SM_HS 0
#define SM_WS (ROWS * HS_STRIDE * 2)               // 66048
#define SMEM_REC (SM_WS + 64 * HS_STRIDE * 2)      // 198144

__global__ void __launch_bounds__(256, 1) k_rec(const float* __restrict__ W,
                                                float* __restrict__ out) {
    extern __shared__ __align__(16) char smem[];
    __half (*Hs)[HS_STRIDE] = (__half(*)[HS_STRIDE])(smem + SM_HS);   // [32][1032]
    __half (*Ws)[HS_STRIDE] = (__half(*)[HS_STRIDE])(smem + SM_WS);   // [64][1032]
    float* gsm = (float*)(smem + SM_HS);           // [4][32][65] floats, aliases Hs

    int g   = blockIdx.x >> 6;                     // group 0/1
    int c   = blockIdx.x & 63;                     // CTA index within group
    int tid = threadIdx.x, lane = tid & 31, warp = tid >> 5;
    int wk  = warp >> 1;                           // K-quarter 0..3
    int wn  = warp & 1;                            // n-half 0..1
    int cb  = wk * 256;

    // resident weight slice: Ws[loc][k] = W[(loc>>4)*1024 + c*16 + (loc&15)][k]
    for (int idx = tid; idx < 64 * 1024; idx += 256) {
        int loc = idx >> 10, k = idx & 1023;
        int wrow = ((loc >> 4) << 10) + c * 16 + (loc & 15);
        Ws[loc][k] = __float2half(W[(size_t)wrow * 2048 + k]);
    }
    __syncthreads();

    // elementwise ownership: em = batch row (0..31), units ej0, ej0+1 (of 16)
    int em = tid >> 3, ej0 = (tid & 7) * 2;
    float C0 = 0.0f, C1 = 0.0f;
    const float* gxbase = g_Gx + ((size_t)c * NB + g * ROWS + em) * 64 + ej0;

    // prologue: gx for t=0
    float2 gxr[4];
#pragma unroll
    for (int q = 0; q < 4; ++q) gxr[q] = *(const float2*)(gxbase + q * 16);

    for (int t = 0; t < LSEQ; ++t) {
        // stage own 128 H cols in 2 x 64-col groups (rows 0..31)
        const __half* Hg = g_Hbuf[t & 1] + (size_t)g * ROWS * 1024;
#pragma unroll
        for (int ch = 0; ch < 2; ++ch) {
            int colbase = cb + wn * 128 + ch * 64;
#pragma unroll
            for (int i = 0; i < 8; ++i) {
                int idx = i * 32 + lane;           // 0..255
                int row = idx >> 3;
                int col = colbase + (idx & 7) * 8;
                cp16(&Hs[row][col], Hg + row * 1024 + col);
            }
            cp_commit();
        }

        float acc[2][4][4];
#pragma unroll
        for (int a = 0; a < 2; ++a)
#pragma unroll
            for (int b = 0; b < 4; ++b)
#pragma unroll
                for (int cc = 0; cc < 4; ++cc) acc[a][b][cc] = 0.0f;

        // phase 0: own half, overlapped with the second refill group
#pragma unroll
        for (int sub = 0; sub < 2; ++sub) {
            if (sub == 0) cp_wait<1>(); else cp_wait<0>();
            __syncwarp();
            int k0b = cb + wn * 128 + sub * 64;
#pragma unroll
            for (int kt = 0; kt < 4; ++kt) {
                int k0 = k0b + kt * 16;
                unsigned a[2][4];
#pragma unroll
                for (int mt = 0; mt < 2; ++mt)
                    ldmatrix_x4(a[mt], smem_u32(&Hs[mt * 16 + (lane & 15)]
                                                  [k0 + (lane >> 4) * 8]));
#pragma unroll
                for (int bg = 0; bg < 2; ++bg) {
                    unsigned b[4];
                    ldmatrix_x4(b, smem_u32(&Ws[wn * 32 + bg * 16 + ((lane >> 4) << 3) + (lane & 7)]
                                              [k0 + ((lane >> 3) & 1) * 8]));
#pragma unroll
                    for (int mt = 0; mt < 2; ++mt) {
                        mma16816(acc[mt][bg * 2],     a[mt], b[0], b[1]);
                        mma16816(acc[mt][bg * 2 + 1], a[mt], b[2], b[3]);
                    }
                }
            }
        }

        // pair sync: partner's 128 cols staged & stable
        asm volatile("bar.sync %0, 64;" :: "r"(1 + wk) : "memory");

        // phase 1: partner half
        {
            int k0b = cb + (1 - wn) * 128;
#pragma unroll 4
            for (int kt = 0; kt < 8; ++kt) {
                int k0 = k0b + kt * 16;
                unsigned a[2][4];
#pragma unroll
                for (int mt = 0; mt < 2; ++mt)
                    ldmatrix_x4(a[mt], smem_u32(&Hs[mt * 16 + (lane & 15)]
                                                  [k0 + (lane >> 4) * 8]));
#pragma unroll
                for (int bg = 0; bg < 2; ++bg) {
                    unsigned b[4];
                    ldmatrix_x4(b, smem_u32(&Ws[wn * 32 + bg * 16 + ((lane >> 4) << 3) + (lane & 7)]
                                              [k0 + ((lane >> 3) & 1) * 8]));
#pragma unroll
                    for (int mt = 0; mt < 2; ++mt) {
                        mma16816(acc[mt][bg * 2],     a[mt], b[0], b[1]);
                        mma16816(acc[mt][bg * 2 + 1], a[mt], b[2], b[3]);
                    }
                }
            }
        }

        // all Hs reads done before gsm (alias) is written
        __syncthreads();
        {
            float* gp = gsm + wk * (32 * 65);
            int mrow = lane >> 2;
            int ncol = wn * 32 + ((lane & 3) << 1);
#pragma unroll
            for (int mt = 0; mt < 2; ++mt)
#pragma unroll
                for (int ng = 0; ng < 4; ++ng) {
                    const float* cc = acc[mt][ng];
                    int m = mrow + mt * 16, n = ncol + ng * 8;
                    gp[m * 65 + n]           = cc[0];
                    gp[m * 65 + n + 1]       = cc[1];
                    gp[(m + 8) * 65 + n]     = cc[2];
                    gp[(m + 8) * 65 + n + 1] = cc[3];
                }
        }
        __syncthreads();

        // elementwise: 4-way K-reduction + LSTM cell (fast MUFU transcendentals)
        float s[4][2];
#pragma unroll
        for (int q = 0; q < 4; ++q) {
            float v0 = gxr[q].x, v1 = gxr[q].y;
            int base = em * 65 + q * 16 + ej0;
#pragma unroll
            for (int kq = 0; kq < 4; ++kq) {
                v0 += gsm[kq * (32 * 65) + base];
                v1 += gsm[kq * (32 * 65) + base + 1];
            }
            s[q][0] = v0; s[q][1] = v1;
        }
        float i0 = sigf(s[0][0]), f0 = sigf(s[1][0]), o0 = sigf(s[2][0]), gg0 = tanhfast(s[3][0]);
        float i1 = sigf(s[0][1]), f1 = sigf(s[1][1]), o1 = sigf(s[2][1]), gg1 = tanhfast(s[3][1]);
        C0 = f0 * C0 + i0 * gg0;
        C1 = f1 * C1 + i1 * gg1;
        float h0 = o0 * tanhfast(C0), h1 = o1 * tanhfast(C1);

        __half* Hn = g_Hbuf[(t & 1) ^ 1];
        int grow = g * ROWS + em;
        int hcol = c * 16 + ej0;
        *(__half2*)(Hn + grow * 1024 + hcol) = __floats2half2_rn(h0, h1);
        if (t == LSEQ - 1) {
            float2 ov; ov.x = h0; ov.y = h1;
            *(float2*)(out + grow * 1024 + hcol) = ov;
        }

        // prefetch next step's gx (hides LDG under barrier)
        int tn = (t + 1 < LSEQ) ? (t + 1) : t;
        const float* gxp = gxbase + (size_t)tn * CPG * NB * 64;
#pragma unroll
        for (int q = 0; q < 4; ++q) gxr[q] = *(const float2*)(gxp + q * 16);

        // grid barrier: release-RMW arrival (no membar), tid0 acquire-poll,
        // CTA-wide wake via syncthreads; skipped entirely after the last step
        if (t + 1 < LSEQ) {
            __syncthreads();
            if (tid == 0) {
                int* barp = &g_bar[g * LSEQ + t];
                red_release(barp, 1);
                while (ld_acquire(barp) < CPG) { }
            }
            __syncthreads();
        }
    }
}

// ---------------- launch ----------------------------------------------------------
extern "C" void kernel_launch(void* const* d_in, const int* in_sizes, int n_in,
                              void* d_out, int out_size) {
    (void)in_sizes; (void)n_in; (void)out_size;
    const int*   X  = (const int*)d_in[0];
    const float* E  = (const float*)d_in[1];
    const float* W  = (const float*)d_in[2];
    const float* Wb = (const float*)d_in[3];
    float* out = (float*)d_out;

    cudaFuncSetAttribute(k_rec, cudaFuncAttributeMaxDynamicSharedMemorySize, SMEM_REC);
    cudaFuncSetAttribute(k_gx, cudaFuncAttributeMaxDynamicSharedMemorySize, GX_SMEM);

    k_cvt_e<<<2048, 256>>>(E);
    k_pack<<<1024, 256>>>(W, Wb);
    k_gx<<<dim3(32, 256), 256, GX_SMEM>>>(X);
    k_rec<<<NCTA, 256, SMEM_REC>>>(W, out);
}

// round 16
// speedup vs baseline: 1.4497x; 1.0504x over previous
#include <cuda_runtime.h>
#include <cuda_fp16.h>
#include <cstdint>

#define VOCABSZ 32000
#define EMBD    1024
#define HID     1024
#define G4      4096
#define NB      64
#define LSEQ    512
#define NCTA    128
#define NGRP    2          // batch groups
#define CPG     64         // CTAs per group
#define ROWS    32         // batch rows per group

// ---------------- device scratch (static; no cudaMalloc allowed) ----------------
__device__ __half g_Eb[(size_t)VOCABSZ * EMBD];          // E as fp16 (64 MB)
__device__ __half g_Bx[(size_t)G4 * 1024];               // W_x^T, [colp][k], gate-permuted (8 MB)
__device__ float  g_bias[G4];                            // permuted bias
__device__ float  g_Gx[(size_t)LSEQ * G4 * NB];          // x-gates, [t][c][n][loc64]
__device__ __half g_Hbuf[2][NB * HID];                   // H double buffer (fp16)
__device__ int    g_bar[NGRP * LSEQ];                    // per-group per-step counters

// gate-column permutation: colp = c*64 + loc ; gate = loc>>4, unit = c*16 + (loc&15)
__device__ __forceinline__ int perm_row(int colp) {
    int c = colp >> 6, loc = colp & 63;
    return ((loc >> 4) << 10) + c * 16 + (loc & 15);
}

// ---------------- mma / ldmatrix / cp.async helpers -----------------------------
__device__ __forceinline__ unsigned smem_u32(const void* p) {
    return (unsigned)__cvta_generic_to_shared(p);
}
__device__ __forceinline__ void ldmatrix_x4(unsigned* r, unsigned addr) {
    asm volatile("ldmatrix.sync.aligned.m8n8.x4.shared.b16 {%0,%1,%2,%3}, [%4];"
                 : "=r"(r[0]), "=r"(r[1]), "=r"(r[2]), "=r"(r[3]) : "r"(addr));
}
__device__ __forceinline__ void mma16816(float* d, const unsigned* a, unsigned b0, unsigned b1) {
    asm volatile("mma.sync.aligned.m16n8k16.row.col.f32.f16.f16.f32 "
                 "{%0,%1,%2,%3}, {%4,%5,%6,%7}, {%8,%9}, {%0,%1,%2,%3};"
                 : "+f"(d[0]), "+f"(d[1]), "+f"(d[2]), "+f"(d[3])
                 : "r"(a[0]), "r"(a[1]), "r"(a[2]), "r"(a[3]), "r"(b0), "r"(b1));
}
__device__ __forceinline__ void cp16(void* s, const void* g) {
    asm volatile("cp.async.cg.shared.global [%0], [%1], 16;"
                 :: "r"(smem_u32(s)), "l"(g) : "memory");
}
__device__ __forceinline__ void cp_commit() { asm volatile("cp.async.commit_group;" ::: "memory"); }
template <int N>
__device__ __forceinline__ void cp_wait() { asm volatile("cp.async.wait_group %0;" :: "n"(N) : "memory"); }

__device__ __forceinline__ void red_release(int* p, int v) {
    asm volatile("red.release.gpu.global.add.u32 [%0], %1;" :: "l"(p), "r"(v) : "memory");
}
__device__ __forceinline__ int ld_acquire(const int* p) {
    int v;
    asm volatile("ld.global.acquire.gpu.b32 %0, [%1];" : "=r"(v) : "l"(p) : "memory");
    return v;
}
// fast transcendentals (MUFU-based): ~2 ulp, far below the fp16 noise floor
__device__ __forceinline__ float sigf(float x) {
    return __fdividef(1.0f, 1.0f + __expf(-x));
}
__device__ __forceinline__ float tanhfast(float x) {
    float e = __expf(2.0f * x);
    return 1.0f - __fdividef(2.0f, e + 1.0f);
}

// ---------------- prep: E -> fp16 ------------------------------------------------
__global__ __launch_bounds__(256) void k_cvt_e(const float* __restrict__ E) {
    size_t total8 = (size_t)VOCABSZ * EMBD / 8;
    size_t stride = (size_t)gridDim.x * blockDim.x;
    for (size_t i = (size_t)blockIdx.x * blockDim.x + threadIdx.x; i < total8; i += stride) {
        const float4* s = (const float4*)(E + i * 8);
        float4 v0 = s[0], v1 = s[1];
        __half2 h0 = __floats2half2_rn(v0.x, v0.y);
        __half2 h1 = __floats2half2_rn(v0.z, v0.w);
        __half2 h2 = __floats2half2_rn(v1.x, v1.y);
        __half2 h3 = __floats2half2_rn(v1.z, v1.w);
        uint4 o;
        o.x = *(unsigned*)&h0; o.y = *(unsigned*)&h1;
        o.z = *(unsigned*)&h2; o.w = *(unsigned*)&h3;
        ((uint4*)g_Eb)[i] = o;
    }
}

// ---------------- prep: pack Bx, bias, reset barriers & H0 -----------------------
__global__ __launch_bounds__(256) void k_pack(const float* __restrict__ W,
                                              const float* __restrict__ Wb) {
    int i0 = blockIdx.x * blockDim.x + threadIdx.x;
    int stride = gridDim.x * blockDim.x;
    for (int idx = i0; idx < G4 * 1024; idx += stride) {
        int colp = idx >> 10, k = idx & 1023;
        g_Bx[idx] = __float2half(W[(size_t)perm_row(colp) * 2048 + 1024 + k]);
    }
    for (int idx = i0; idx < G4; idx += stride) g_bias[idx] = Wb[perm_row(idx)];
    for (int idx = i0; idx < NGRP * LSEQ; idx += stride) g_bar[idx] = 0;
    for (int idx = i0; idx < NB * HID; idx += stride) g_Hbuf[0][idx] = __float2half(0.0f);
}

// ---------------- phase 1: Gx = embed(X) @ Wx^T + b (R12/R15-proven) --------------
#define GX_STG  4
#define GX_STR  40
#define GX_TILE (128 * GX_STR)
#define GX_SMEM (GX_STG * 2 * GX_TILE * 2)       // 81920 B

__global__ __launch_bounds__(256, 2) void k_gx(const int* __restrict__ X) {
    extern __shared__ __align__(16) __half dsm[];
    __half* As = dsm;
    __half* Bs = dsm + GX_STG * GX_TILE;
    __shared__ int   toks[128];
    __shared__ float bsm[128];

    int tid = threadIdx.x, lane = tid & 31, warp = tid >> 5;
    int wm = warp >> 1, wn = warp & 1;
    int mblk = blockIdx.y * 128, nblk = blockIdx.x * 128;

    if (tid < 128) {
        int m = mblk + tid;                      // m = t*64 + n
        toks[tid] = X[(m & 63) * LSEQ + (m >> 6)];
        bsm[tid] = g_bias[nblk + tid];
    }
    __syncthreads();

    auto issue = [&](int c) {
        __half* Ab = As + (c & (GX_STG - 1)) * GX_TILE;
        __half* Bb = Bs + (c & (GX_STG - 1)) * GX_TILE;
        int k0 = c * 32;
#pragma unroll
        for (int i = 0; i < 2; ++i) {
            int idx = tid + i * 256;
            int row = idx >> 2, q = idx & 3;
            cp16(Ab + row * GX_STR + q * 8,
                 &g_Eb[(size_t)toks[row] * EMBD + k0 + q * 8]);
        }
#pragma unroll
        for (int i = 0; i < 2; ++i) {
            int idx = tid + i * 256;
            int row = idx >> 2, q = idx & 3;
            cp16(Bb + row * GX_STR + q * 8,
                 &g_Bx[(size_t)(nblk + row) * 1024 + k0 + q * 8]);
        }
        cp_commit();
    };

    float acc[2][8][4];
#pragma unroll
    for (int a = 0; a < 2; ++a)
#pragma unroll
        for (int b = 0; b < 8; ++b)
#pragma unroll
            for (int c = 0; c < 4; ++c) acc[a][b][c] = 0.0f;

    issue(0); issue(1); issue(2);

    for (int c = 0; c < 32; ++c) {
        if (c < 30)       cp_wait<2>();
        else if (c == 30) cp_wait<1>();
        else              cp_wait<0>();
        __syncthreads();

        if (c + 3 < 32) issue(c + 3);

        const __half* Ab = As + (c & (GX_STG - 1)) * GX_TILE;
        const __half* Bb = Bs + (c & (GX_STG - 1)) * GX_TILE;
#pragma unroll
        for (int ks = 0; ks < 2; ++ks) {
            unsigned a[2][4];
#pragma unroll
            for (int mt = 0; mt < 2; ++mt)
                ldmatrix_x4(a[mt], smem_u32(Ab + (wm * 32 + mt * 16 + (lane & 15)) * GX_STR
                                               + ks * 16 + (lane >> 4) * 8));
#pragma unroll
            for (int nt = 0; nt < 4; ++nt) {     // x4 B: 16 n-rows per ldsm
                unsigned b[4];
                ldmatrix_x4(b, smem_u32(Bb + (wn * 64 + nt * 16 + ((lane >> 4) << 3) + (lane & 7)) * GX_STR
                                           + ks * 16 + ((lane >> 3) & 1) * 8));
                mma16816(acc[0][nt * 2],     a[0], b[0], b[1]);
                mma16816(acc[1][nt * 2],     a[1], b[0], b[1]);
                mma16816(acc[0][nt * 2 + 1], a[0], b[2], b[3]);
                mma16816(acc[1][nt * 2 + 1], a[1], b[2], b[3]);
            }
        }
    }

    // epilogue: add bias, store Gx[t][c][n][loc64]
#pragma unroll
    for (int mt = 0; mt < 2; ++mt) {
#pragma unroll
        for (int nt = 0; nt < 8; ++nt) {
            int mrow = mblk + wm * 32 + mt * 16 + (lane >> 2);
            int cloc = wn * 64 + nt * 8 + ((lane & 3) << 1);
            int colp = nblk + cloc;
            float b0 = bsm[cloc], b1 = bsm[cloc + 1];
            const float* c = acc[mt][nt];
#pragma unroll
            for (int rr = 0; rr < 2; ++rr) {
                int m = mrow + rr * 8;
                int t = m >> 6, n = m & 63;
                size_t off = (((size_t)t * CPG + (colp >> 6)) * NB + n) * 64 + (colp & 63);
                float2 v; v.x = c[rr * 2] + b0; v.y = c[rr * 2 + 1] + b1;
                *(float2*)&g_Gx[off] = v;
            }
        }
    }
}

// ---------------- phase 2: persistent recurrent kernel (R15 + dedicated gsm) -----
// gsm no longer aliases Hs -> the post-mma alias-guard syncthreads is REMOVED:
// each warp stores its K-partials immediately after its own phase-1 mma.
#define HS_STRIDE 1032
#define SM_HS 0
#define SM_WS (ROWS * HS_STRIDE * 2)               // 66048
#define SM_GS (SM_WS + 64 * HS_STRIDE * 2)         // 198144
#define SMEM_REC (SM_GS + 4 * 32 * 65 * 4)         // 231424

__global__ void __launch_bounds__(256, 1) k_rec(const float* __restrict__ W,
                                                float* __restrict__ out) {
    extern __shared__ __align__(16) char smem[];
    __half (*Hs)[HS_STRIDE] = (__half(*)[HS_STRIDE])(smem + SM_HS);   // [32][1032]
    __half (*Ws)[HS_STRIDE] = (__half(*)[HS_STRIDE])(smem + SM_WS);   // [64][1032]
    float* gsm = (float*)(smem + SM_GS);           // [4][32][65] floats (dedicated)

    int g   = blockIdx.x >> 6;                     // group 0/1
    int c   = blockIdx.x & 63;                     // CTA index within group
    int tid = threadIdx.x, lane = tid & 31, warp = tid >> 5;
    int wk  = warp >> 1;                           // K-quarter 0..3
    int wn  = warp & 1;                            // n-half 0..1
    int cb  = wk * 256;

    // resident weight slice: Ws[loc][k] = W[(loc>>4)*1024 + c*16 + (loc&15)][k]
    for (int idx = tid; idx < 64 * 1024; idx += 256) {
        int loc = idx >> 10, k = idx & 1023;
        int wrow = ((loc >> 4) << 10) + c * 16 + (loc & 15);
        Ws[loc][k] = __float2half(W[(size_t)wrow * 2048 + k]);
    }
    __syncthreads();

    // elementwise ownership: em = batch row (0..31), units ej0, ej0+1 (of 16)
    int em = tid >> 3, ej0 = (tid & 7) * 2;
    float C0 = 0.0f, C1 = 0.0f;
    const float* gxbase = g_Gx + ((size_t)c * NB + g * ROWS + em) * 64 + ej0;

    // prologue: gx for t=0
    float2 gxr[4];
#pragma unroll
    for (int q = 0; q < 4; ++q) gxr[q] = *(const float2*)(gxbase + q * 16);

    for (int t = 0; t < LSEQ; ++t) {
        // stage own 128 H cols in 2 x 64-col groups (rows 0..31)
        const __half* Hg = g_Hbuf[t & 1] + (size_t)g * ROWS * 1024;
#pragma unroll
        for (int ch = 0; ch < 2; ++ch) {
            int colbase = cb + wn * 128 + ch * 64;
#pragma unroll
            for (int i = 0; i < 8; ++i) {
                int idx = i * 32 + lane;           // 0..255
                int row = idx >> 3;
                int col = colbase + (idx & 7) * 8;
                cp16(&Hs[row][col], Hg + row * 1024 + col);
            }
            cp_commit();
        }

        float acc[2][4][4];
#pragma unroll
        for (int a = 0; a < 2; ++a)
#pragma unroll
            for (int b = 0; b < 4; ++b)
#pragma unroll
                for (int cc = 0; cc < 4; ++cc) acc[a][b][cc] = 0.0f;

        // phase 0: own half, overlapped with the second refill group
#pragma unroll
        for (int sub = 0; sub < 2; ++sub) {
            if (sub == 0) cp_wait<1>(); else cp_wait<0>();
            __syncwarp();
            int k0b = cb + wn * 128 + sub * 64;
#pragma unroll
            for (int kt = 0; kt < 4; ++kt) {
                int k0 = k0b + kt * 16;
                unsigned a[2][4];
#pragma unroll
                for (int mt = 0; mt < 2; ++mt)
                    ldmatrix_x4(a[mt], smem_u32(&Hs[mt * 16 + (lane & 15)]
                                                  [k0 + (lane >> 4) * 8]));
#pragma unroll
                for (int bg = 0; bg < 2; ++bg) {
                    unsigned b[4];
                    ldmatrix_x4(b, smem_u32(&Ws[wn * 32 + bg * 16 + ((lane >> 4) << 3) + (lane & 7)]
                                              [k0 + ((lane >> 3) & 1) * 8]));
#pragma unroll
                    for (int mt = 0; mt < 2; ++mt) {
                        mma16816(acc[mt][bg * 2],     a[mt], b[0], b[1]);
                        mma16816(acc[mt][bg * 2 + 1], a[mt], b[2], b[3]);
                    }
                }
            }
        }

        // pair sync: partner's 128 cols staged & stable
        asm volatile("bar.sync %0, 64;" :: "r"(1 + wk) : "memory");

        // phase 1: partner half
        {
            int k0b = cb + (1 - wn) * 128;
#pragma unroll 4
            for (int kt = 0; kt < 8; ++kt) {
                int k0 = k0b + kt * 16;
                unsigned a[2][4];
#pragma unroll
                for (int mt = 0; mt < 2; ++mt)
                    ldmatrix_x4(a[mt], smem_u32(&Hs[mt * 16 + (lane & 15)]
                                                  [k0 + (lane >> 4) * 8]));
#pragma unroll
                for (int bg = 0; bg < 2; ++bg) {
                    unsigned b[4];
                    ldmatrix_x4(b, smem_u32(&Ws[wn * 32 + bg * 16 + ((lane >> 4) << 3) + (lane & 7)]
                                              [k0 + ((lane >> 3) & 1) * 8]));
#pragma unroll
                    for (int mt = 0; mt < 2; ++mt) {
                        mma16816(acc[mt][bg * 2],     a[mt], b[0], b[1]);
                        mma16816(acc[mt][bg * 2 + 1], a[mt], b[2], b[3]);
                    }
                }
            }
        }

        // exchange: write K-partials directly (dedicated gsm, no alias guard)
        {
            float* gp = gsm + wk * (32 * 65);
            int mrow = lane >> 2;
            int ncol = wn * 32 + ((lane & 3) << 1);
#pragma unroll
            for (int mt = 0; mt < 2; ++mt)
#pragma unroll
                for (int ng = 0; ng < 4; ++ng) {
                    const float* cc = acc[mt][ng];
                    int m = mrow + mt * 16, n = ncol + ng * 8;
                    gp[m * 65 + n]           = cc[0];
                    gp[m * 65 + n + 1]       = cc[1];
                    gp[(m + 8) * 65 + n]     = cc[2];
                    gp[(m + 8) * 65 + n + 1] = cc[3];
                }
        }
        __syncthreads();

        // elementwise: 4-way K-reduction + LSTM cell (fast MUFU transcendentals)
        float s[4][2];
#pragma unroll
        for (int q = 0; q < 4; ++q) {
            float v0 = gxr[q].x, v1 = gxr[q].y;
            int base = em * 65 + q * 16 + ej0;
#pragma unroll
            for (int kq = 0; kq < 4; ++kq) {
                v0 += gsm[kq * (32 * 65) + base];
                v1 += gsm[kq * (32 * 65) + base + 1];
            }
            s[q][0] = v0; s[q][1] = v1;
        }
        float i0 = sigf(s[0][0]), f0 = sigf(s[1][0]), o0 = sigf(s[2][0]), gg0 = tanhfast(s[3][0]);
        float i1 = sigf(s[0][1]), f1 = sigf(s[1][1]), o1 = sigf(s[2][1]), gg1 = tanhfast(s[3][1]);
        C0 = f0 * C0 + i0 * gg0;
        C1 = f1 * C1 + i1 * gg1;
        float h0 = o0 * tanhfast(C0), h1 = o1 * tanhfast(C1);

        __half* Hn = g_Hbuf[(t & 1) ^ 1];
        int grow = g * ROWS + em;
        int hcol = c * 16 + ej0;
        *(__half2*)(Hn + grow * 1024 + hcol) = __floats2half2_rn(h0, h1);
        if (t == LSEQ - 1) {
            float2 ov; ov.x = h0; ov.y = h1;
            *(float2*)(out + grow * 1024 + hcol) = ov;
        }

        // prefetch next step's gx (hides LDG under barrier)
        int tn = (t + 1 < LSEQ) ? (t + 1) : t;
        const float* gxp = gxbase + (size_t)tn * CPG * NB * 64;
#pragma unroll
        for (int q = 0; q < 4; ++q) gxr[q] = *(const float2*)(gxp + q * 16);

        // grid barrier: release-RMW arrival (no membar), tid0 acquire-poll,
        // CTA-wide wake via syncthreads; skipped entirely after the last step
        if (t + 1 < LSEQ) {
            __syncthreads();
            if (tid == 0) {
                int* barp = &g_bar[g * LSEQ + t];
                red_release(barp, 1);
                while (ld_acquire(barp) < CPG) { }
            }
            __syncthreads();
        }
    }
}

// ---------------- launch ----------------------------------------------------------
extern "C" void kernel_launch(void* const* d_in, const int* in_sizes, int n_in,
                              void* d_out, int out_size) {
    (void)in_sizes; (void)n_in; (void)out_size;
    const int*   X  = (const int*)d_in[0];
    const float* E  = (const float*)d_in[1];
    const float* W  = (const float*)d_in[2];
    const float* Wb = (const float*)d_in[3];
    float* out = (float*)d_out;

    cudaFuncSetAttribute(k_rec, cudaFuncAttributeMaxDynamicSharedMemorySize, SMEM_REC);
    cudaFuncSetAttribute(k_gx, cudaFuncAttributeMaxDynamicSharedMemorySize, GX_SMEM);

    k_cvt_e<<<2048, 256>>>(E);
    k_pack<<<1024, 256>>>(W, Wb);
    k_gx<<<dim3(32, 256), 256, GX_SMEM>>>(X);
    k_rec<<<NCTA, 256, SMEM_REC>>>(W, out);
}